// round 4
// baseline (speedup 1.0000x reference)
#include <cuda_runtime.h>

// ---------------------------------------------------------------------------
// BinaryTreeLSTM  (B=64, L=2048, H=DW=128, V=100000)
//
//   h0 = emb[word_ids] @ W_wh                    (131072 x 128x128 gather-GEMM)
//   repeat 11x:  s = (hl+hr) @ W_hh + 2*b_hh     (pairs x 128x640 matvec)
//                gates -> h
//
// fp32 everywhere, packed fma.rn.f32x2 in the hot k-loops.
// ---------------------------------------------------------------------------

#define BB   64
#define LL   2048
#define HH   128

// scratch (device globals: no allocations allowed)
__device__ float g_h0[BB * LL * HH];        // 67 MB
__device__ float g_h1[BB * (LL / 2) * HH];  // 33.5 MB

static __device__ __forceinline__ unsigned long long pack2(float lo, float hi) {
    unsigned long long r;
    asm("mov.b64 %0, {%1, %2};" : "=l"(r) : "f"(lo), "f"(hi));
    return r;
}
static __device__ __forceinline__ void unpack2(unsigned long long v, float& lo, float& hi) {
    asm("mov.b64 {%0, %1}, %2;" : "=f"(lo), "=f"(hi) : "l"(v));
}
static __device__ __forceinline__ unsigned long long fma2(
    unsigned long long a, unsigned long long b, unsigned long long c) {
    unsigned long long d;
    asm("fma.rn.f32x2 %0, %1, %2, %3;" : "=l"(d) : "l"(a), "l"(b), "l"(c));
    return d;
}
static __device__ __forceinline__ float sigmoidf_(float x) {
    return 1.0f / (1.0f + expf(-x));
}

// ---------------------------------------------------------------------------
// Phase 1: h0[row][c] = sum_k emb[word_ids[row]][k] * W_wh[k][c]
// block: 256 threads, 32 rows. W (64KB) + E rows (16KB) in dynamic smem.
// thread: colquad q = t&31 (cols 4q..4q+3), rowgroup rg = t>>5 (rows rg*4..+3)
// ---------------------------------------------------------------------------
__global__ void __launch_bounds__(256)
embed_proj_kernel(const int* __restrict__ wid, const float* __restrict__ emb,
                  const float* __restrict__ Wwh, float* __restrict__ hout)
{
    extern __shared__ float smem[];
    float* Ws = smem;                 // 128*128
    float* Es = smem + 128 * 128;     // 32*128
    __shared__ int wids[32];

    const int t = threadIdx.x;
    const int rowbase = blockIdx.x * 32;

    if (t < 32) wids[t] = wid[rowbase + t];

    // load W_wh -> smem (coalesced float4)
    const float4* W4g = (const float4*)Wwh;
    float4* Ws4 = (float4*)Ws;
    #pragma unroll
    for (int i = t; i < 128 * 32; i += 256) Ws4[i] = W4g[i];
    __syncthreads();

    // gather 32 embedding rows -> smem
    const float4* emb4 = (const float4*)emb;
    float4* Es4 = (float4*)Es;
    #pragma unroll
    for (int i = t; i < 32 * 32; i += 256) {
        int r = i >> 5, qq = i & 31;
        Es4[i] = emb4[(size_t)wids[r] * 32 + qq];
    }
    __syncthreads();

    const int q  = t & 31;
    const int rg = t >> 5;

    unsigned long long acc[4][2] = {};   // [row][colpair], 0ull == {0.f,0.f}
    const ulonglong2* Wv = (const ulonglong2*)Ws;   // [k*32 + q]

    #pragma unroll 2
    for (int k = 0; k < 128; k++) {
        ulonglong2 w = Wv[k * 32 + q];
        #pragma unroll
        for (int r = 0; r < 4; r++) {
            float ev = Es[(rg * 4 + r) * 128 + k];
            unsigned long long e2 = pack2(ev, ev);
            acc[r][0] = fma2(w.x, e2, acc[r][0]);
            acc[r][1] = fma2(w.y, e2, acc[r][1]);
        }
    }

    #pragma unroll
    for (int r = 0; r < 4; r++) {
        float4 o;
        unpack2(acc[r][0], o.x, o.y);
        unpack2(acc[r][1], o.z, o.w);
        ((float4*)hout)[(size_t)(rowbase + rg * 4 + r) * 32 + q] = o;
    }
}

// ---------------------------------------------------------------------------
// Tree level: for each pair (b,j):  x = h[b][2j] + h[b][2j+1]
//   s = x @ W_hh + 2*b_hh ; gates ; hout[b][j] = o * tanh(c)
// block: 256 threads, 16 pairs. x/hl/hr staged in smem (24KB).
// thread: colquad q = t&31, pairgroup pg = t>>5 -> pairs 2pg, 2pg+1.
// k-loop: 5x LDG.128 (W row, L2-resident) + 20 fma.f32x2 per k.
// ---------------------------------------------------------------------------
#define PAIRS 16

__global__ void __launch_bounds__(256)
tree_level_kernel(const float* __restrict__ hin, float* __restrict__ hout,
                  const float* __restrict__ Whh, const float* __restrict__ bhh,
                  int n, int halfn, int totalPairs)
{
    __shared__ float xs [PAIRS][128];
    __shared__ float hls[PAIRS][128];
    __shared__ float hrs[PAIRS][128];

    const int t = threadIdx.x;
    const int base = blockIdx.x * PAIRS;

    #pragma unroll
    for (int i = t; i < PAIRS * 128; i += 256) {
        int p = i >> 7, c = i & 127;
        int pair = base + p;
        float hl = 0.f, hr = 0.f;
        if (pair < totalPairs) {
            int b = pair / halfn;
            int j = pair - b * halfn;
            size_t off = ((size_t)b * n + 2 * j) * HH + c;
            hl = hin[off];
            hr = hin[off + HH];
        }
        hls[p][c] = hl;
        hrs[p][c] = hr;
        xs [p][c] = hl + hr;
    }
    __syncthreads();

    const int q  = t & 31;
    const int pg = t >> 5;
    const int p0 = pg * 2, p1 = pg * 2 + 1;

    unsigned long long acc[2][5][2] = {};
    const ulonglong2* Wv = (const ulonglong2*)Whh;  // row k: 160 x 16B

    #pragma unroll 2
    for (int k = 0; k < 128; k++) {
        ulonglong2 w[5];
        #pragma unroll
        for (int g = 0; g < 5; g++) w[g] = Wv[k * 160 + g * 32 + q];

        float x0 = xs[p0][k];
        float x1 = xs[p1][k];
        unsigned long long e0 = pack2(x0, x0);
        unsigned long long e1 = pack2(x1, x1);

        #pragma unroll
        for (int g = 0; g < 5; g++) {
            acc[0][g][0] = fma2(w[g].x, e0, acc[0][g][0]);
            acc[0][g][1] = fma2(w[g].y, e0, acc[0][g][1]);
            acc[1][g][0] = fma2(w[g].x, e1, acc[1][g][0]);
            acc[1][g][1] = fma2(w[g].y, e1, acc[1][g][1]);
        }
    }

    // bias quads per gate
    float4 bv[5];
    #pragma unroll
    for (int g = 0; g < 5; g++) bv[g] = ((const float4*)bhh)[g * 32 + q];

    #pragma unroll
    for (int pl = 0; pl < 2; pl++) {
        int pair = base + pg * 2 + pl;
        if (pair >= totalPairs) continue;
        int b = pair / halfn;
        int j = pair - b * halfn;

        float s[5][4];
        #pragma unroll
        for (int g = 0; g < 5; g++) {
            unpack2(acc[pl][g][0], s[g][0], s[g][1]);
            unpack2(acc[pl][g][1], s[g][2], s[g][3]);
        }
        const float* bvf0 = &bv[0].x;
        const float* bvf1 = &bv[1].x;
        const float* bvf2 = &bv[2].x;
        const float* bvf3 = &bv[3].x;
        const float* bvf4 = &bv[4].x;

        float4 ho;
        float* hop = &ho.x;
        #pragma unroll
        for (int jj = 0; jj < 4; jj++) {
            int col = 4 * q + jj;
            float i_g  = sigmoidf_(s[0][jj] + 2.0f * bvf0[jj]);
            float lf_g = sigmoidf_(s[1][jj] + 2.0f * bvf1[jj]);
            float rf_g = sigmoidf_(s[2][jj] + 2.0f * bvf2[jj]);
            float o_g  = sigmoidf_(s[3][jj] + 2.0f * bvf3[jj]);
            float g_v  = tanhf    (s[4][jj] + 2.0f * bvf4[jj]);
            float hl = hls[pg * 2 + pl][col];
            float hr = hrs[pg * 2 + pl][col];
            float c  = i_g * g_v + lf_g * hl + rf_g * hr;
            hop[jj] = o_g * tanhf(c);
        }
        ((float4*)hout)[((size_t)b * halfn + j) * 32 + q] = ho;
    }
}

// ---------------------------------------------------------------------------
extern "C" void kernel_launch(void* const* d_in, const int* in_sizes, int n_in,
                              void* d_out, int out_size)
{
    const int*   wid = (const int*)  d_in[0];   // (B, L) int32
    const float* emb = (const float*)d_in[1];   // (V, DW)
    const float* Wwh = (const float*)d_in[2];   // (DW, H)
    const float* Whh = (const float*)d_in[3];   // (H, 5H)
    const float* bhh = (const float*)d_in[4];   // (5H,)
    float* out = (float*)d_out;                 // (B, 1, H)

    float *h0, *h1;
    cudaGetSymbolAddress((void**)&h0, g_h0);
    cudaGetSymbolAddress((void**)&h1, g_h1);

    const size_t smem1 = (size_t)(128 * 128 + 32 * 128) * sizeof(float);  // 80KB
    cudaFuncSetAttribute(embed_proj_kernel,
                         cudaFuncAttributeMaxDynamicSharedMemorySize, (int)smem1);

    // Phase 1: gather + projection into h0
    embed_proj_kernel<<<(BB * LL) / 32, 256, smem1>>>(wid, emb, Wwh, h0);

    // Phase 2: 11 tree levels, ping-pong h0/h1, last level writes d_out
    const float* cur = h0;
    float* alt = h1;
    for (int n = LL; n > 1; n >>= 1) {
        int halfn = n >> 1;
        int pairs = BB * halfn;
        float* o = (n == 2) ? out : alt;
        int blocks = (pairs + PAIRS - 1) / PAIRS;
        tree_level_kernel<<<blocks, 256>>>(cur, o, Whh, bhh, n, halfn, pairs);
        alt = (float*)cur;
        cur = o;
    }
}

// round 6
// speedup vs baseline: 2.0857x; 2.0857x over previous
#include <cuda_runtime.h>
#include <cuda_bf16.h>
#include <cstdint>

// ---------------------------------------------------------------------------
// BinaryTreeLSTM  (B=64, L=2048, H=DW=128, V=100000) — mma.sync split-bf16
//
// Phase 1:  h0 = emb[word_ids] @ W_wh        (M=131072, K=128, N=128)
// Tree x11: s = (hl+hr) @ W_hh + 2*b_hh      (M=pairs,  K=128, N=640) ; gates
//
// Split-bf16: x = x_hi + x_lo, W = W_hi + W_lo
//   s ~= x_hi@W_hi + x_hi@W_lo + x_lo@W_hi   (3 bf16 passes, fp32 accum)
// W_hh column-reordered: tile tt (N=160) = cols tt*32..+31 of ALL 5 gates.
// NOTE: tcgen05 is unavailable (harness targets sm_103 without 'a');
// mma.sync.m16n8k16 bf16 is the legal tensor-core path here.
// ---------------------------------------------------------------------------

#define BB 64
#define LL 2048
#define HH 128
#define MAXP (BB * LL / 2)

__device__ float g_h0[BB * LL * HH];             // 67 MB
__device__ float g_h1[MAXP * HH];                // 33.5 MB
__device__ __nv_bfloat16 g_xhi[MAXP * HH];
__device__ __nv_bfloat16 g_xlo[MAXP * HH];
__device__ __nv_bfloat16 g_WrHi[4 * 160 * 128];  // reordered W_hh^T hi
__device__ __nv_bfloat16 g_WrLo[4 * 160 * 128];  // reordered W_hh^T lo
__device__ __nv_bfloat16 g_WtHi[128 * 128];      // W_wh^T hi
__device__ __nv_bfloat16 g_WtLo[128 * 128];      // W_wh^T lo

// ---------------------------------------------------------------- helpers
static __device__ __forceinline__ uint32_t smem_u32(const void* p) {
    uint32_t a;
    asm("{ .reg .u64 t; cvta.to.shared.u64 t, %1; cvt.u32.u64 %0, t; }"
        : "=r"(a) : "l"(p));
    return a;
}
// XOR-swizzled byte offset: rows of 256B, 16B chunks permuted by (row&7)
static __device__ __forceinline__ uint32_t swz(int row, int kb) {
    return (uint32_t)(row * 256 + (kb ^ ((row & 7) << 4)));
}
static __device__ __forceinline__ void ldmx4(uint32_t* r, uint32_t a) {
    asm volatile("ldmatrix.sync.aligned.m8n8.x4.shared.b16 {%0,%1,%2,%3}, [%4];"
                 : "=r"(r[0]), "=r"(r[1]), "=r"(r[2]), "=r"(r[3]) : "r"(a));
}
static __device__ __forceinline__ void ldmx2(uint32_t* r, uint32_t a) {
    asm volatile("ldmatrix.sync.aligned.m8n8.x2.shared.b16 {%0,%1}, [%2];"
                 : "=r"(r[0]), "=r"(r[1]) : "r"(a));
}
static __device__ __forceinline__ void mma_bf16(float* d, const uint32_t* a,
                                                const uint32_t* b) {
    asm volatile(
        "mma.sync.aligned.m16n8k16.row.col.f32.bf16.bf16.f32 "
        "{%0,%1,%2,%3}, {%4,%5,%6,%7}, {%8,%9}, {%0,%1,%2,%3};"
        : "+f"(d[0]), "+f"(d[1]), "+f"(d[2]), "+f"(d[3])
        : "r"(a[0]), "r"(a[1]), "r"(a[2]), "r"(a[3]), "r"(b[0]), "r"(b[1]));
}
static __device__ __forceinline__ void split_bf16(float x, unsigned short& h,
                                                  unsigned short& l) {
    __nv_bfloat16 hi = __float2bfloat16(x);
    __nv_bfloat16 lo = __float2bfloat16(x - __bfloat162float(hi));
    h = __bfloat16_as_ushort(hi);
    l = __bfloat16_as_ushort(lo);
}
static __device__ __forceinline__ float sg(float x) {
    return __fdividef(1.0f, 1.0f + __expf(-x));
}
static __device__ __forceinline__ float th(float x) {
    return __fdividef(2.0f, 1.0f + __expf(-2.0f * x)) - 1.0f;
}

// ---------------------------------------------------------------- weight prep
__global__ void prep_weights(const float* __restrict__ Whh,
                             const float* __restrict__ Wwh) {
    int idx = blockIdx.x * 256 + threadIdx.x;
    if (idx < 4 * 160 * 128) {
        int tt = idx / (160 * 128);
        int rem = idx - tt * 160 * 128;
        int row = rem >> 7, k = rem & 127;     // row = g*32+cc
        int g = row >> 5, cc = row & 31;
        float w = Whh[(size_t)k * 640 + g * 128 + tt * 32 + cc];
        unsigned short h, l; split_bf16(w, h, l);
        g_WrHi[idx] = __ushort_as_bfloat16(h);
        g_WrLo[idx] = __ushort_as_bfloat16(l);
    } else if (idx < 4 * 160 * 128 + 128 * 128) {
        int j = idx - 4 * 160 * 128;
        int n = j >> 7, k = j & 127;
        float w = Wwh[(size_t)k * 128 + n];
        unsigned short h, l; split_bf16(w, h, l);
        g_WtHi[j] = __ushort_as_bfloat16(h);
        g_WtLo[j] = __ushort_as_bfloat16(l);
    }
}

// ---------------------------------------------------------------- x prep
__global__ void __launch_bounds__(256)
prep_x(const float* __restrict__ hin, int P) {
    int idx = blockIdx.x * 256 + threadIdx.x;   // one float4 (4 cols)
    int p = idx >> 5, c4 = idx & 31;
    if (p >= P) return;
    const float4* h4 = (const float4*)hin;
    float4 a = h4[(size_t)p * 64 + c4];
    float4 b = h4[(size_t)p * 64 + 32 + c4];
    ushort4 vh, vl;
    split_bf16(a.x + b.x, vh.x, vl.x);
    split_bf16(a.y + b.y, vh.y, vl.y);
    split_bf16(a.z + b.z, vh.z, vl.z);
    split_bf16(a.w + b.w, vh.w, vl.w);
    ((ushort4*)g_xhi)[idx] = vh;
    ((ushort4*)g_xlo)[idx] = vl;
}

// ---------------------------------------------------------------- tree GEMM
// smem: Xhi 32KB | Xlo 32KB | Whi 40KB | Wlo 40KB  = 144KB; S reuses (82KB)
#define TS_XHI 0
#define TS_XLO 32768
#define TS_WHI 65536
#define TS_WLO (65536 + 40960)
#define TS_TOTAL (65536 + 81920)
#define SST 164   // S row stride in floats (164 % 32 == 4: conflict-free)

__global__ void __launch_bounds__(256)
tree_mma(const float* __restrict__ hin, float* __restrict__ hout,
         const float* __restrict__ bhh, int P)
{
    extern __shared__ char smem[];
    const uint32_t sb = smem_u32(smem);
    const int t = threadIdx.x, wid = t >> 5, lane = t & 31;
    const int Mbase = blockIdx.x * 128;
    const int tt = blockIdx.y;

    // stage W tile (160 x 128 bf16, hi+lo)
    {
        const uint4* sH = (const uint4*)(g_WrHi + tt * 160 * 128);
        const uint4* sL = (const uint4*)(g_WrLo + tt * 160 * 128);
        #pragma unroll
        for (int i = t; i < 2560; i += 256) {
            int row = i >> 4;
            uint32_t off = swz(row, (i & 15) << 4);
            *(uint4*)(smem + TS_WHI + off) = sH[i];
            *(uint4*)(smem + TS_WLO + off) = sL[i];
        }
    }
    // stage X tile (128 x 128 bf16, hi+lo), zero-pad rows >= P
    {
        #pragma unroll
        for (int i = t; i < 2048; i += 256) {
            int row = i >> 4;
            int p = Mbase + row;
            uint4 vh = make_uint4(0, 0, 0, 0), vl = vh;
            if (p < P) {
                vh = ((const uint4*)g_xhi)[p * 16 + (i & 15)];
                vl = ((const uint4*)g_xlo)[p * 16 + (i & 15)];
            }
            uint32_t off = swz(row, (i & 15) << 4);
            *(uint4*)(smem + TS_XHI + off) = vh;
            *(uint4*)(smem + TS_XLO + off) = vl;
        }
    }
    __syncthreads();

    // warp tile: 2(M) x 4(N) -> 64 rows x 40 cols
    const int mw = (wid & 1) * 64, nw = (wid >> 1) * 40;
    float acc[4][5][4];
    #pragma unroll
    for (int mi = 0; mi < 4; mi++)
        #pragma unroll
        for (int nj = 0; nj < 5; nj++)
            #pragma unroll
            for (int r = 0; r < 4; r++) acc[mi][nj][r] = 0.0f;

    const int la = lane & 15;
    const int arow_off = mw + la;          // + mi*16
    const int akb_off = (lane >> 4) * 16;  // + kstep*32
    const int brow_off = nw + (la & 7);    // + nj*8
    const int bkb_off = (la >> 3) * 16;    // + kstep*32

    #pragma unroll
    for (int ks = 0; ks < 8; ks++) {
        uint32_t ah[4][4], al[4][4];
        #pragma unroll
        for (int mi = 0; mi < 4; mi++) {
            int row = arow_off + mi * 16;
            uint32_t off = swz(row, akb_off + ks * 32);
            ldmx4(ah[mi], sb + TS_XHI + off);
            ldmx4(al[mi], sb + TS_XLO + off);
        }
        #pragma unroll
        for (int nj = 0; nj < 5; nj++) {
            int nrow = brow_off + nj * 8;
            uint32_t off = swz(nrow, bkb_off + ks * 32);
            uint32_t bh[2], bl[2];
            ldmx2(bh, sb + TS_WHI + off);
            ldmx2(bl, sb + TS_WLO + off);
            #pragma unroll
            for (int mi = 0; mi < 4; mi++) {
                mma_bf16(acc[mi][nj], ah[mi], bh);   // hi*hi
                mma_bf16(acc[mi][nj], ah[mi], bl);   // hi*lo
                mma_bf16(acc[mi][nj], al[mi], bh);   // lo*hi
            }
        }
    }
    __syncthreads();   // staging no longer needed; reuse smem for S

    // scatter S (rows 128 x cols 160, fp32) to smem
    float* S = (float*)smem;
    {
        const int r0 = mw + (lane >> 2);
        const int c0 = nw + (lane & 3) * 2;
        #pragma unroll
        for (int mi = 0; mi < 4; mi++)
            #pragma unroll
            for (int nj = 0; nj < 5; nj++) {
                int row = r0 + mi * 16, col = c0 + nj * 8;
                *(float2*)&S[row * SST + col] =
                    make_float2(acc[mi][nj][0], acc[mi][nj][1]);
                *(float2*)&S[(row + 8) * SST + col] =
                    make_float2(acc[mi][nj][2], acc[mi][nj][3]);
            }
    }
    __syncthreads();

    // fused gate epilogue: thread -> col cc=lane, rows wid*16..+15
    {
        const int cb = tt * 32;
        const int cc = lane;
        float b0 = 2.0f * bhh[0 * HH + cb + cc];
        float b1 = 2.0f * bhh[1 * HH + cb + cc];
        float b2 = 2.0f * bhh[2 * HH + cb + cc];
        float b3 = 2.0f * bhh[3 * HH + cb + cc];
        float b4 = 2.0f * bhh[4 * HH + cb + cc];
        #pragma unroll
        for (int rr = 0; rr < 16; rr++) {
            int row = wid * 16 + rr;
            int p = Mbase + row;
            if (p >= P) break;
            const float* Sr = S + row * SST + cc;
            float ig = sg(Sr[0]   + b0);
            float lf = sg(Sr[32]  + b1);
            float rf = sg(Sr[64]  + b2);
            float og = sg(Sr[96]  + b3);
            float gg = th(Sr[128] + b4);
            float hl = hin[(size_t)(2 * p) * HH + cb + cc];
            float hr = hin[(size_t)(2 * p) * HH + HH + cb + cc];
            float c = ig * gg + lf * hl + rf * hr;
            hout[(size_t)p * HH + cb + cc] = og * th(c);
        }
    }
}

// ---------------------------------------------------------------- embed GEMM
// smem: Xhi 32KB | Xlo 32KB | Whi 32KB | Wlo 32KB = 128KB; S reuses (66KB)
#define ES_XHI 0
#define ES_XLO 32768
#define ES_WHI 65536
#define ES_WLO 98304
#define ES_TOTAL 131072
#define EST 132   // S row stride (132 % 32 == 4)

__global__ void __launch_bounds__(256)
embed_mma(const int* __restrict__ wids_g, const float* __restrict__ emb,
          float* __restrict__ hout)
{
    extern __shared__ char smem[];
    __shared__ int wids_s[128];
    const uint32_t sb = smem_u32(smem);
    const int t = threadIdx.x, wid = t >> 5, lane = t & 31;
    const int Mbase = blockIdx.x * 128;

    if (t < 128) wids_s[t] = wids_g[Mbase + t];

    // stage W (128 x 128 bf16, hi+lo)
    {
        const uint4* sH = (const uint4*)g_WtHi;
        const uint4* sL = (const uint4*)g_WtLo;
        #pragma unroll
        for (int i = t; i < 2048; i += 256) {
            int row = i >> 4;
            uint32_t off = swz(row, (i & 15) << 4);
            *(uint4*)(smem + ES_WHI + off) = sH[i];
            *(uint4*)(smem + ES_WLO + off) = sL[i];
        }
    }
    __syncthreads();   // wids_s ready

    // gather + split E rows
    {
        #pragma unroll
        for (int i = t; i < 2048; i += 256) {
            int row = i >> 4, kc = (i & 15) * 8;      // 8 floats
            const float4* e4 =
                (const float4*)(emb + (size_t)wids_s[row] * 128 + kc);
            float4 a = e4[0], b = e4[1];
            ushort4 vh0, vl0, vh1, vl1;
            split_bf16(a.x, vh0.x, vl0.x); split_bf16(a.y, vh0.y, vl0.y);
            split_bf16(a.z, vh0.z, vl0.z); split_bf16(a.w, vh0.w, vl0.w);
            split_bf16(b.x, vh1.x, vl1.x); split_bf16(b.y, vh1.y, vl1.y);
            split_bf16(b.z, vh1.z, vl1.z); split_bf16(b.w, vh1.w, vl1.w);
            uint32_t off = swz(row, (i & 15) << 4);
            *(ushort4*)(smem + ES_XHI + off) = vh0;
            *(ushort4*)(smem + ES_XHI + off + 8) = vh1;
            *(ushort4*)(smem + ES_XLO + off) = vl0;
            *(ushort4*)(smem + ES_XLO + off + 8) = vl1;
        }
    }
    __syncthreads();

    // warp tile: 2(M) x 4(N) -> 64 rows x 32 cols
    const int mw = (wid & 1) * 64, nw = (wid >> 1) * 32;
    float acc[4][4][4];
    #pragma unroll
    for (int mi = 0; mi < 4; mi++)
        #pragma unroll
        for (int nj = 0; nj < 4; nj++)
            #pragma unroll
            for (int r = 0; r < 4; r++) acc[mi][nj][r] = 0.0f;

    const int la = lane & 15;
    const int arow_off = mw + la;
    const int akb_off = (lane >> 4) * 16;
    const int brow_off = nw + (la & 7);
    const int bkb_off = (la >> 3) * 16;

    #pragma unroll
    for (int ks = 0; ks < 8; ks++) {
        uint32_t ah[4][4], al[4][4];
        #pragma unroll
        for (int mi = 0; mi < 4; mi++) {
            int row = arow_off + mi * 16;
            uint32_t off = swz(row, akb_off + ks * 32);
            ldmx4(ah[mi], sb + ES_XHI + off);
            ldmx4(al[mi], sb + ES_XLO + off);
        }
        #pragma unroll
        for (int nj = 0; nj < 4; nj++) {
            int nrow = brow_off + nj * 8;
            uint32_t off = swz(nrow, bkb_off + ks * 32);
            uint32_t bh[2], bl[2];
            ldmx2(bh, sb + ES_WHI + off);
            ldmx2(bl, sb + ES_WLO + off);
            #pragma unroll
            for (int mi = 0; mi < 4; mi++) {
                mma_bf16(acc[mi][nj], ah[mi], bh);
                mma_bf16(acc[mi][nj], ah[mi], bl);
                mma_bf16(acc[mi][nj], al[mi], bh);
            }
        }
    }
    __syncthreads();

    // S -> smem -> coalesced float4 stores
    float* S = (float*)smem;
    {
        const int r0 = mw + (lane >> 2);
        const int c0 = nw + (lane & 3) * 2;
        #pragma unroll
        for (int mi = 0; mi < 4; mi++)
            #pragma unroll
            for (int nj = 0; nj < 4; nj++) {
                int row = r0 + mi * 16, col = c0 + nj * 8;
                *(float2*)&S[row * EST + col] =
                    make_float2(acc[mi][nj][0], acc[mi][nj][1]);
                *(float2*)&S[(row + 8) * EST + col] =
                    make_float2(acc[mi][nj][2], acc[mi][nj][3]);
            }
    }
    __syncthreads();
    {
        #pragma unroll
        for (int i = t; i < 4096; i += 256) {       // 128 rows x 32 float4
            int row = i >> 5, c4 = i & 31;
            float4 v = *(const float4*)&S[row * EST + c4 * 4];
            ((float4*)hout)[(size_t)(Mbase + row) * 32 + c4] = v;
        }
    }
}

// ---------------------------------------------------------------------------
extern "C" void kernel_launch(void* const* d_in, const int* in_sizes, int n_in,
                              void* d_out, int out_size)
{
    const int*   wid = (const int*)  d_in[0];   // (B, L)
    const float* emb = (const float*)d_in[1];   // (V, DW)
    const float* Wwh = (const float*)d_in[2];   // (DW, H)
    const float* Whh = (const float*)d_in[3];   // (H, 5H)
    const float* bhh = (const float*)d_in[4];   // (5H,)
    float* out = (float*)d_out;                 // (B, 1, H)

    float *h0, *h1;
    cudaGetSymbolAddress((void**)&h0, g_h0);
    cudaGetSymbolAddress((void**)&h1, g_h1);

    cudaFuncSetAttribute(tree_mma,  cudaFuncAttributeMaxDynamicSharedMemorySize, TS_TOTAL);
    cudaFuncSetAttribute(embed_mma, cudaFuncAttributeMaxDynamicSharedMemorySize, ES_TOTAL);

    prep_weights<<<(4 * 160 * 128 + 128 * 128 + 255) / 256, 256>>>(Whh, Wwh);

    // Phase 1: gather-GEMM -> h0
    embed_mma<<<(BB * LL) / 128, 256, ES_TOTAL>>>(wid, emb, h0);

    // Phase 2: 11 tree levels
    const float* cur = h0;
    float* alt = h1;
    for (int n = LL; n > 1; n >>= 1) {
        int halfn = n >> 1;
        int P = BB * halfn;
        prep_x<<<(P * 32 + 255) / 256, 256>>>(cur, P);
        float* o = (n == 2) ? out : alt;
        dim3 grid((P + 127) / 128, 4);
        tree_mma<<<grid, 256, TS_TOTAL>>>(cur, o, bhh, P);
        alt = (float*)cur;
        cur = o;
    }
}

// round 7
// speedup vs baseline: 2.7800x; 1.3329x over previous
#include <cuda_runtime.h>
#include <cuda_bf16.h>
#include <cstdint>

// ---------------------------------------------------------------------------
// BinaryTreeLSTM  (B=64, L=2048, H=DW=128, V=100000) — mma.sync split-bf16
//
// Phase 1:  h0 = emb[word_ids] @ W_wh        (M=131072, K=128, N=128)
// Tree x11: s = (hl+hr) @ W_hh + 2*b_hh      (M=pairs,  K=128, N=640) ; gates
//
// Split-bf16: x = x_hi + x_lo, W = W_hi + W_lo
//   s ~= x_hi@W_hi + x_hi@W_lo + x_lo@W_hi   (3 bf16 passes, fp32 accum)
// W_hh column-reordered: tile tt (N=160) = cols tt*32..+31 of ALL 5 gates.
// R7: 512-thread CTAs (16 warps, 4Mx4N) for 2x occupancy; prep_x fused into
// tree_mma staging (load hl/hr fp32, add+split in-kernel).
// ---------------------------------------------------------------------------

#define BB 64
#define LL 2048
#define HH 128
#define MAXP (BB * LL / 2)

__device__ float g_h0[BB * LL * HH];             // 67 MB
__device__ float g_h1[MAXP * HH];                // 33.5 MB
__device__ __nv_bfloat16 g_WrHi[4 * 160 * 128];  // reordered W_hh^T hi
__device__ __nv_bfloat16 g_WrLo[4 * 160 * 128];  // reordered W_hh^T lo
__device__ __nv_bfloat16 g_WtHi[128 * 128];      // W_wh^T hi
__device__ __nv_bfloat16 g_WtLo[128 * 128];      // W_wh^T lo

// ---------------------------------------------------------------- helpers
static __device__ __forceinline__ uint32_t smem_u32(const void* p) {
    uint32_t a;
    asm("{ .reg .u64 t; cvta.to.shared.u64 t, %1; cvt.u32.u64 %0, t; }"
        : "=r"(a) : "l"(p));
    return a;
}
// XOR-swizzled byte offset: rows of 256B, 16B chunks permuted by (row&7)
static __device__ __forceinline__ uint32_t swz(int row, int kb) {
    return (uint32_t)(row * 256 + (kb ^ ((row & 7) << 4)));
}
static __device__ __forceinline__ void ldmx4(uint32_t* r, uint32_t a) {
    asm volatile("ldmatrix.sync.aligned.m8n8.x4.shared.b16 {%0,%1,%2,%3}, [%4];"
                 : "=r"(r[0]), "=r"(r[1]), "=r"(r[2]), "=r"(r[3]) : "r"(a));
}
static __device__ __forceinline__ void ldmx2(uint32_t* r, uint32_t a) {
    asm volatile("ldmatrix.sync.aligned.m8n8.x2.shared.b16 {%0,%1}, [%2];"
                 : "=r"(r[0]), "=r"(r[1]) : "r"(a));
}
static __device__ __forceinline__ void mma_bf16(float* d, const uint32_t* a,
                                                const uint32_t* b) {
    asm volatile(
        "mma.sync.aligned.m16n8k16.row.col.f32.bf16.bf16.f32 "
        "{%0,%1,%2,%3}, {%4,%5,%6,%7}, {%8,%9}, {%0,%1,%2,%3};"
        : "+f"(d[0]), "+f"(d[1]), "+f"(d[2]), "+f"(d[3])
        : "r"(a[0]), "r"(a[1]), "r"(a[2]), "r"(a[3]), "r"(b[0]), "r"(b[1]));
}
static __device__ __forceinline__ void split_bf16(float x, unsigned short& h,
                                                  unsigned short& l) {
    __nv_bfloat16 hi = __float2bfloat16(x);
    __nv_bfloat16 lo = __float2bfloat16(x - __bfloat162float(hi));
    h = __bfloat16_as_ushort(hi);
    l = __bfloat16_as_ushort(lo);
}
static __device__ __forceinline__ float sg(float x) {
    return __fdividef(1.0f, 1.0f + __expf(-x));
}
static __device__ __forceinline__ float th(float x) {
    return __fdividef(2.0f, 1.0f + __expf(-2.0f * x)) - 1.0f;
}

// ---------------------------------------------------------------- weight prep
__global__ void prep_weights(const float* __restrict__ Whh,
                             const float* __restrict__ Wwh) {
    int idx = blockIdx.x * 256 + threadIdx.x;
    if (idx < 4 * 160 * 128) {
        int tt = idx / (160 * 128);
        int rem = idx - tt * 160 * 128;
        int row = rem >> 7, k = rem & 127;     // row = g*32+cc
        int g = row >> 5, cc = row & 31;
        float w = Whh[(size_t)k * 640 + g * 128 + tt * 32 + cc];
        unsigned short h, l; split_bf16(w, h, l);
        g_WrHi[idx] = __ushort_as_bfloat16(h);
        g_WrLo[idx] = __ushort_as_bfloat16(l);
    } else if (idx < 4 * 160 * 128 + 128 * 128) {
        int j = idx - 4 * 160 * 128;
        int n = j >> 7, k = j & 127;
        float w = Wwh[(size_t)k * 128 + n];
        unsigned short h, l; split_bf16(w, h, l);
        g_WtHi[j] = __ushort_as_bfloat16(h);
        g_WtLo[j] = __ushort_as_bfloat16(l);
    }
}

// ---------------------------------------------------------------- tree GEMM
// 512 threads, 16 warps as 4(M) x 4(N); warp tile 32 rows x 40 cols.
// smem: Xhi 32KB | Xlo 32KB | Whi 40KB | Wlo 40KB = 144KB; S reuses (82KB)
#define TS_XHI 0
#define TS_XLO 32768
#define TS_WHI 65536
#define TS_WLO (65536 + 40960)
#define TS_TOTAL (65536 + 81920)
#define SST 164   // S row stride in floats (164 % 32 == 4: conflict-free)

__global__ void __launch_bounds__(512)
tree_mma(const float* __restrict__ hin, float* __restrict__ hout,
         const float* __restrict__ bhh, int P)
{
    extern __shared__ char smem[];
    const uint32_t sb = smem_u32(smem);
    const int t = threadIdx.x, wid = t >> 5, lane = t & 31;
    const int Mbase = blockIdx.x * 128;
    const int tt = blockIdx.y;

    // stage W tile (160 x 128 bf16, hi+lo)
    {
        const uint4* sH = (const uint4*)(g_WrHi + tt * 160 * 128);
        const uint4* sL = (const uint4*)(g_WrLo + tt * 160 * 128);
        #pragma unroll
        for (int i = t; i < 2560; i += 512) {
            int row = i >> 4;
            uint32_t off = swz(row, (i & 15) << 4);
            *(uint4*)(smem + TS_WHI + off) = sH[i];
            *(uint4*)(smem + TS_WLO + off) = sL[i];
        }
    }
    // stage X tile fused: x = hl + hr (fp32) -> split bf16 hi/lo -> smem
    {
        #pragma unroll
        for (int i = t; i < 2048; i += 512) {
            int row = i >> 4, kc = (i & 15) * 8;   // 8 k-floats per chunk
            int p = Mbase + row;
            ushort4 vh0 = make_ushort4(0,0,0,0), vl0 = vh0, vh1 = vh0, vl1 = vh0;
            if (p < P) {
                const float4* hl4 = (const float4*)(hin + (size_t)(2 * p) * HH + kc);
                const float4* hr4 = (const float4*)(hin + (size_t)(2 * p) * HH + HH + kc);
                float4 a0 = hl4[0], a1 = hl4[1];
                float4 b0 = hr4[0], b1 = hr4[1];
                split_bf16(a0.x + b0.x, vh0.x, vl0.x);
                split_bf16(a0.y + b0.y, vh0.y, vl0.y);
                split_bf16(a0.z + b0.z, vh0.z, vl0.z);
                split_bf16(a0.w + b0.w, vh0.w, vl0.w);
                split_bf16(a1.x + b1.x, vh1.x, vl1.x);
                split_bf16(a1.y + b1.y, vh1.y, vl1.y);
                split_bf16(a1.z + b1.z, vh1.z, vl1.z);
                split_bf16(a1.w + b1.w, vh1.w, vl1.w);
            }
            uint32_t off = swz(row, (i & 15) << 4);
            *(ushort4*)(smem + TS_XHI + off) = vh0;
            *(ushort4*)(smem + TS_XHI + off + 8) = vh1;
            *(ushort4*)(smem + TS_XLO + off) = vl0;
            *(ushort4*)(smem + TS_XLO + off + 8) = vl1;
        }
    }
    __syncthreads();

    // warp tile: (wid>>2) of 4 M-tiles (32 rows), (wid&3) of 4 N-tiles (40 cols)
    const int mw = (wid >> 2) * 32, nw = (wid & 3) * 40;
    float acc[2][5][4];
    #pragma unroll
    for (int mi = 0; mi < 2; mi++)
        #pragma unroll
        for (int nj = 0; nj < 5; nj++)
            #pragma unroll
            for (int r = 0; r < 4; r++) acc[mi][nj][r] = 0.0f;

    const int la = lane & 15;
    const int arow_off = mw + la;          // + mi*16
    const int akb_off = (lane >> 4) * 16;  // + kstep*32
    const int brow_off = nw + (la & 7);    // + nj*8
    const int bkb_off = (la >> 3) * 16;    // + kstep*32

    #pragma unroll
    for (int ks = 0; ks < 8; ks++) {
        uint32_t ah[2][4], al[2][4];
        #pragma unroll
        for (int mi = 0; mi < 2; mi++) {
            int row = arow_off + mi * 16;
            uint32_t off = swz(row, akb_off + ks * 32);
            ldmx4(ah[mi], sb + TS_XHI + off);
            ldmx4(al[mi], sb + TS_XLO + off);
        }
        #pragma unroll
        for (int nj = 0; nj < 5; nj++) {
            int nrow = brow_off + nj * 8;
            uint32_t off = swz(nrow, bkb_off + ks * 32);
            uint32_t bh[2], bl[2];
            ldmx2(bh, sb + TS_WHI + off);
            ldmx2(bl, sb + TS_WLO + off);
            #pragma unroll
            for (int mi = 0; mi < 2; mi++) {
                mma_bf16(acc[mi][nj], ah[mi], bh);   // hi*hi
                mma_bf16(acc[mi][nj], ah[mi], bl);   // hi*lo
                mma_bf16(acc[mi][nj], al[mi], bh);   // lo*hi
            }
        }
    }
    __syncthreads();   // staging no longer needed; reuse smem for S

    // scatter S (rows 128 x cols 160, fp32) to smem
    float* S = (float*)smem;
    {
        const int r0 = mw + (lane >> 2);
        const int c0 = nw + (lane & 3) * 2;
        #pragma unroll
        for (int mi = 0; mi < 2; mi++)
            #pragma unroll
            for (int nj = 0; nj < 5; nj++) {
                int row = r0 + mi * 16, col = c0 + nj * 8;
                *(float2*)&S[row * SST + col] =
                    make_float2(acc[mi][nj][0], acc[mi][nj][1]);
                *(float2*)&S[(row + 8) * SST + col] =
                    make_float2(acc[mi][nj][2], acc[mi][nj][3]);
            }
    }
    __syncthreads();

    // fused gate epilogue: thread -> col cc=lane, rows wid*8..+7
    {
        const int cb = tt * 32;
        const int cc = lane;
        float b0 = 2.0f * bhh[0 * HH + cb + cc];
        float b1 = 2.0f * bhh[1 * HH + cb + cc];
        float b2 = 2.0f * bhh[2 * HH + cb + cc];
        float b3 = 2.0f * bhh[3 * HH + cb + cc];
        float b4 = 2.0f * bhh[4 * HH + cb + cc];
        #pragma unroll
        for (int rr = 0; rr < 8; rr++) {
            int row = wid * 8 + rr;
            int p = Mbase + row;
            if (p >= P) break;
            const float* Sr = S + row * SST + cc;
            float ig = sg(Sr[0]   + b0);
            float lf = sg(Sr[32]  + b1);
            float rf = sg(Sr[64]  + b2);
            float og = sg(Sr[96]  + b3);
            float gg = th(Sr[128] + b4);
            float hl = hin[(size_t)(2 * p) * HH + cb + cc];
            float hr = hin[(size_t)(2 * p) * HH + HH + cb + cc];
            float c = ig * gg + lf * hl + rf * hr;
            hout[(size_t)p * HH + cb + cc] = og * th(c);
        }
    }
}

// ---------------------------------------------------------------- embed GEMM
// 512 threads, 16 warps as 4(M) x 4(N); warp tile 32 rows x 32 cols.
// smem: Xhi 32KB | Xlo 32KB | Whi 32KB | Wlo 32KB = 128KB; S reuses (66KB)
#define ES_XHI 0
#define ES_XLO 32768
#define ES_WHI 65536
#define ES_WLO 98304
#define ES_TOTAL 131072
#define EST 132   // S row stride (132 % 32 == 4)

__global__ void __launch_bounds__(512)
embed_mma(const int* __restrict__ wids_g, const float* __restrict__ emb,
          float* __restrict__ hout)
{
    extern __shared__ char smem[];
    __shared__ int wids_s[128];
    const uint32_t sb = smem_u32(smem);
    const int t = threadIdx.x, wid = t >> 5, lane = t & 31;
    const int Mbase = blockIdx.x * 128;

    if (t < 128) wids_s[t] = wids_g[Mbase + t];

    // stage W (128 x 128 bf16, hi+lo)
    {
        const uint4* sH = (const uint4*)g_WtHi;
        const uint4* sL = (const uint4*)g_WtLo;
        #pragma unroll
        for (int i = t; i < 2048; i += 512) {
            int row = i >> 4;
            uint32_t off = swz(row, (i & 15) << 4);
            *(uint4*)(smem + ES_WHI + off) = sH[i];
            *(uint4*)(smem + ES_WLO + off) = sL[i];
        }
    }
    __syncthreads();   // wids_s ready

    // gather + split E rows
    {
        #pragma unroll
        for (int i = t; i < 2048; i += 512) {
            int row = i >> 4, kc = (i & 15) * 8;      // 8 floats
            const float4* e4 =
                (const float4*)(emb + (size_t)wids_s[row] * 128 + kc);
            float4 a = e4[0], b = e4[1];
            ushort4 vh0, vl0, vh1, vl1;
            split_bf16(a.x, vh0.x, vl0.x); split_bf16(a.y, vh0.y, vl0.y);
            split_bf16(a.z, vh0.z, vl0.z); split_bf16(a.w, vh0.w, vl0.w);
            split_bf16(b.x, vh1.x, vl1.x); split_bf16(b.y, vh1.y, vl1.y);
            split_bf16(b.z, vh1.z, vl1.z); split_bf16(b.w, vh1.w, vl1.w);
            uint32_t off = swz(row, (i & 15) << 4);
            *(ushort4*)(smem + ES_XHI + off) = vh0;
            *(ushort4*)(smem + ES_XHI + off + 8) = vh1;
            *(ushort4*)(smem + ES_XLO + off) = vl0;
            *(ushort4*)(smem + ES_XLO + off + 8) = vl1;
        }
    }
    __syncthreads();

    // warp tile: (wid>>2) of 4 M-tiles (32 rows), (wid&3) of 4 N-tiles (32 cols)
    const int mw = (wid >> 2) * 32, nw = (wid & 3) * 32;
    float acc[2][4][4];
    #pragma unroll
    for (int mi = 0; mi < 2; mi++)
        #pragma unroll
        for (int nj = 0; nj < 4; nj++)
            #pragma unroll
            for (int r = 0; r < 4; r++) acc[mi][nj][r] = 0.0f;

    const int la = lane & 15;
    const int arow_off = mw + la;
    const int akb_off = (lane >> 4) * 16;
    const int brow_off = nw + (la & 7);
    const int bkb_off = (la >> 3) * 16;

    #pragma unroll
    for (int ks = 0; ks < 8; ks++) {
        uint32_t ah[2][4], al[2][4];
        #pragma unroll
        for (int mi = 0; mi < 2; mi++) {
            int row = arow_off + mi * 16;
            uint32_t off = swz(row, akb_off + ks * 32);
            ldmx4(ah[mi], sb + ES_XHI + off);
            ldmx4(al[mi], sb + ES_XLO + off);
        }
        #pragma unroll
        for (int nj = 0; nj < 4; nj++) {
            int nrow = brow_off + nj * 8;
            uint32_t off = swz(nrow, bkb_off + ks * 32);
            uint32_t bh[2], bl[2];
            ldmx2(bh, sb + ES_WHI + off);
            ldmx2(bl, sb + ES_WLO + off);
            #pragma unroll
            for (int mi = 0; mi < 2; mi++) {
                mma_bf16(acc[mi][nj], ah[mi], bh);
                mma_bf16(acc[mi][nj], ah[mi], bl);
                mma_bf16(acc[mi][nj], al[mi], bh);
            }
        }
    }
    __syncthreads();

    // S -> smem -> coalesced float4 stores
    float* S = (float*)smem;
    {
        const int r0 = mw + (lane >> 2);
        const int c0 = nw + (lane & 3) * 2;
        #pragma unroll
        for (int mi = 0; mi < 2; mi++)
            #pragma unroll
            for (int nj = 0; nj < 4; nj++) {
                int row = r0 + mi * 16, col = c0 + nj * 8;
                *(float2*)&S[row * EST + col] =
                    make_float2(acc[mi][nj][0], acc[mi][nj][1]);
                *(float2*)&S[(row + 8) * EST + col] =
                    make_float2(acc[mi][nj][2], acc[mi][nj][3]);
            }
    }
    __syncthreads();
    {
        #pragma unroll
        for (int i = t; i < 4096; i += 512) {       // 128 rows x 32 float4
            int row = i >> 5, c4 = i & 31;
            float4 v = *(const float4*)&S[row * EST + c4 * 4];
            ((float4*)hout)[(size_t)(Mbase + row) * 32 + c4] = v;
        }
    }
}

// ---------------------------------------------------------------------------
extern "C" void kernel_launch(void* const* d_in, const int* in_sizes, int n_in,
                              void* d_out, int out_size)
{
    const int*   wid = (const int*)  d_in[0];   // (B, L)
    const float* emb = (const float*)d_in[1];   // (V, DW)
    const float* Wwh = (const float*)d_in[2];   // (DW, H)
    const float* Whh = (const float*)d_in[3];   // (H, 5H)
    const float* bhh = (const float*)d_in[4];   // (5H,)
    float* out = (float*)d_out;                 // (B, 1, H)

    float *h0, *h1;
    cudaGetSymbolAddress((void**)&h0, g_h0);
    cudaGetSymbolAddress((void**)&h1, g_h1);

    cudaFuncSetAttribute(tree_mma,  cudaFuncAttributeMaxDynamicSharedMemorySize, TS_TOTAL);
    cudaFuncSetAttribute(embed_mma, cudaFuncAttributeMaxDynamicSharedMemorySize, ES_TOTAL);

    prep_weights<<<(4 * 160 * 128 + 128 * 128 + 255) / 256, 256>>>(Whh, Wwh);

    // Phase 1: gather-GEMM -> h0
    embed_mma<<<(BB * LL) / 128, 512, ES_TOTAL>>>(wid, emb, h0);

    // Phase 2: 11 tree levels (x-prep fused into tree_mma staging)
    const float* cur = h0;
    float* alt = h1;
    for (int n = LL; n > 1; n >>= 1) {
        int halfn = n >> 1;
        int P = BB * halfn;
        float* o = (n == 2) ? out : alt;
        dim3 grid((P + 127) / 128, 4);
        tree_mma<<<grid, 512, TS_TOTAL>>>(cur, o, bhh, P);
        alt = (float*)cur;
        cur = o;
    }
}